// round 13
// baseline (speedup 1.0000x reference)
#include <cuda_runtime.h>
#include <math.h>

#define NV 1024
#define NB 16
#define GRID_DIM 16                 // 16x16 cells of 25m over [0,400)
#define NCELL (GRID_DIM * GRID_DIM)
#define EPW 8                       // egos per warp (consecutive in sorted order)
#define WPB 2                       // warps per block
#define BTHREADS (WPB * 32)        // 64

// Cell-sorted per-batch data
__device__ float4 g_sxycs[NB * NV];       // {x, y, cos, sin}
__device__ float  g_sv[NB * NV];          // v
__device__ int    g_sorig[NB * NV];       // sorted pos -> original index
__device__ int    g_cstart[NB * (NCELL + 1)];

// One block per batch: sincos + counting-sort into the 16x16 grid.
__global__ __launch_bounds__(512) void prep_kernel(const float* __restrict__ state)
{
    __shared__ int counts[NCELL];
    __shared__ int scan[NCELL];
    __shared__ int offs[NCELL];

    const int bat = blockIdx.x;
    const int t = threadIdx.x;
    const int base = bat * NV;
    const float* st = state + (size_t)bat * NV * 5;

    if (t < NCELL) counts[t] = 0;
    __syncthreads();

    float x[2], y[2], v[2], c[2], s[2];
    int cl[2];
    #pragma unroll
    for (int q = 0; q < 2; q++) {
        int i = t + q * 512;
        const float* p = st + i * 5;
        x[q] = p[0]; y[q] = p[1]; v[q] = p[2];
        float psi = p[3];
        sincosf(psi, &s[q], &c[q]);
        int cx = max(0, min(GRID_DIM - 1, (int)(x[q] * 0.04f)));
        int cy = max(0, min(GRID_DIM - 1, (int)(y[q] * 0.04f)));
        cl[q] = cy * GRID_DIM + cx;
        atomicAdd(&counts[cl[q]], 1);
    }
    __syncthreads();

    if (t < NCELL) scan[t] = counts[t];
    __syncthreads();
    for (int d = 1; d < NCELL; d <<= 1) {
        int val = 0;
        if (t < NCELL && t >= d) val = scan[t - d];
        __syncthreads();
        if (t < NCELL) scan[t] += val;
        __syncthreads();
    }
    if (t < NCELL) {
        int e = scan[t] - counts[t];               // exclusive
        offs[t] = e;
        g_cstart[bat * (NCELL + 1) + t] = e;
    }
    if (t == 0) g_cstart[bat * (NCELL + 1) + NCELL] = NV;
    __syncthreads();

    #pragma unroll
    for (int q = 0; q < 2; q++) {
        int i = t + q * 512;
        int p = atomicAdd(&offs[cl[q]], 1);
        g_sxycs[base + p] = make_float4(x[q], y[q], c[q], s[q]);
        g_sv[base + p] = v[q];
        g_sorig[base + p] = i;
    }
}

// One warp per 8 consecutive SORTED egos (same/adjacent cells -> shared
// neighborhood). Each lane loads one candidate, evaluates vs all 8 egos in
// registers. Certification: outside the per-ego 5x5, dr>=50 => nd>=46.98;
// if best<46.9 the neighborhood result is exact, else lean full-scan fallback.
__global__ __launch_bounds__(BTHREADS)
void rulepolicy_kernel(const float* __restrict__ lengths,
                       const float* __restrict__ v0p,
                       const float* __restrict__ s0p,
                       const float* __restrict__ dthp,
                       const float* __restrict__ amaxp,
                       const float* __restrict__ bp,
                       float* __restrict__ out)
{
    const int lane = threadIdx.x & 31;
    const int wid = threadIdx.x >> 5;
    const int bat = blockIdx.y;
    const int base = bat * NV;
    const int eg0 = (blockIdx.x * WPB + wid) * EPW;   // first sorted ego pos

    const float C20SQ = 0.8830222215594891f;   // cos^2(20deg)
    const float C45   = 0.7071067811865476f;   // cos(45deg)
    const float INF   = __int_as_float(0x7f800000);
    const float TERM  = 46.9f;                 // < 50*cos20 = 46.984

    const int* cs = g_cstart + bat * (NCELL + 1);
    const float4* sd = g_sxycs + base;
    const float*  sv = g_sv + base;

    // Replicate the 8 egos into registers on every lane (L1-broadcast loads);
    // lane e additionally keeps ego e's scalars for the epilogue.
    float ex[EPW], ey[EPW], ec[EPW], es[EPW], ev[EPW];
    float mx = 0, my = 0, mc = 0, ms = 0, mv = 0;
    int   morig = 0;
    int cxmin = GRID_DIM - 1, cxmax = 0, cymin = GRID_DIM - 1, cymax = 0;
    #pragma unroll
    for (int e = 0; e < EPW; e++) {
        float4 a = __ldg(&sd[eg0 + e]);
        float  v = __ldg(&sv[eg0 + e]);
        ex[e] = a.x; ey[e] = a.y; ec[e] = a.z; es[e] = a.w; ev[e] = v;
        if (lane == e) {
            mx = a.x; my = a.y; mc = a.z; ms = a.w; mv = v;
            morig = __ldg(&g_sorig[base + eg0 + e]);
        }
        int cx = max(0, min(GRID_DIM - 1, (int)(a.x * 0.04f)));
        int cy = max(0, min(GRID_DIM - 1, (int)(a.y * 0.04f)));
        cxmin = min(cxmin, cx); cxmax = max(cxmax, cx);
        cymin = min(cymin, cy); cymax = max(cymax, cy);
    }

    float best[EPW];
    int   bidx[EPW];
    unsigned stopm = 0;
    #pragma unroll
    for (int e = 0; e < EPW; e++) { best[e] = INF; bidx[e] = 0; }

    // ── Union neighborhood scan: leader + stop fused, 8 egos per candidate ──
    {
        int x0 = max(cxmin - 2, 0), x1 = min(cxmax + 2, GRID_DIM - 1);
        int y0 = max(cymin - 2, 0), y1 = min(cymax + 2, GRID_DIM - 1);
        for (int ry = y0; ry <= y1; ry++) {
            int beg = __ldg(&cs[ry * GRID_DIM + x0]);
            int end = __ldg(&cs[ry * GRID_DIM + x1 + 1]);
            for (int i = beg + lane; i < end; i += 32) {
                float4 a = __ldg(&sd[i]);
                float vi = __ldg(&sv[i]);
                #pragma unroll
                for (int e = 0; e < EPW; e++) {
                    float dx = a.x - ex[e], dy = a.y - ey[e];
                    float r2 = fmaf(dx, dx, dy * dy);
                    float nd = fmaf(dx, ec[e], dy * es[e]);   // dr*cos(delpsi)
                    float n2 = nd * nd;
                    float m  = fminf(nd, fmaf(-C20SQ, r2, n2));
                    float vv = (m > 0.0f) ? nd : INF;
                    bool  c  = vv < best[e];
                    best[e] = c ? vv : best[e];
                    bidx[e] = c ? i : bidx[e];
                    float cpd = fmaf(a.z, ec[e], a.w * es[e]); // cos(psi_i-psi_j)
                    bool sc = (r2 < 400.0f) & (nd > 0.0f) & (n2 > 0.25f * r2)
                              & (cpd < C45) & (vi > ev[e]);
                    stopm |= sc ? (1u << e) : 0u;
                }
            }
        }
    }

    // ── Reductions: OR the stop mask once; min+tiebreak per ego ──
    #pragma unroll
    for (int m = 1; m <= 16; m <<= 1)
        stopm |= __shfl_xor_sync(0xFFFFFFFFu, stopm, m);

    float rb = 0.0f;  // lane e holds ego e's reduced best (lanes >= EPW: 0)
    int   ri = 0;
    #pragma unroll
    for (int e = 0; e < EPW; e++) {
        float b = best[e]; int ix = bidx[e];
        #pragma unroll
        for (int m = 1; m <= 16; m <<= 1) {
            float ob = __shfl_xor_sync(0xFFFFFFFFu, b, m);
            int   oi = __shfl_xor_sync(0xFFFFFFFFu, ix, m);
            if (ob < b || (ob == b && oi < ix)) { b = ob; ix = oi; }
        }
        if (lane == e) { rb = b; ri = ix; }
    }

    // ── Rare fallback: full lean scan for uncertified egos (warp-uniform) ──
    unsigned need = __ballot_sync(0xFFFFFFFFu, (lane < EPW) && (rb >= TERM));
    if (need) {
        #pragma unroll
        for (int e = 0; e < EPW; e++) {
            if (need & (1u << e)) {
                float b = INF; int ix = 0;
                for (int i = lane; i < NV; i += 32) {
                    float4 a = __ldg(&sd[i]);
                    float dx = a.x - ex[e], dy = a.y - ey[e];
                    float r2 = fmaf(dx, dx, dy * dy);
                    float nd = fmaf(dx, ec[e], dy * es[e]);
                    float m  = fminf(nd, fmaf(-C20SQ, r2, nd * nd));
                    float vv = (m > 0.0f) ? nd : INF;
                    bool  c  = vv < b;
                    b = c ? vv : b;  ix = c ? i : ix;
                }
                #pragma unroll
                for (int m = 1; m <= 16; m <<= 1) {
                    float ob = __shfl_xor_sync(0xFFFFFFFFu, b, m);
                    int   oi = __shfl_xor_sync(0xFFFFFFFFu, ix, m);
                    if (ob < b || (ob == b && oi < ix)) { b = ob; ix = oi; }
                }
                if (lane == e) { rb = b; ri = ix; }
            }
        }
    }

    // ── Epilogue: lane e finishes ego e ──
    if (lane < EPW) {
        const float V0 = __ldg(&v0p[0]), S0 = __ldg(&s0p[0]), DTH = __ldg(&dthp[0]);
        const float AMAX = __ldg(&amaxp[0]), BB = __ldg(&bp[0]);

        float4 ld = __ldg(&sd[ri]);             // leader {x, y, cos, sin}
        float  vl = __ldg(&sv[ri]);
        float dvx = vl * ld.z - mv * mc;
        float dvy = vl * ld.w - mv * ms;
        float ndv = fmaf(dvx, mc, dvy * ms);    // dv*cos(vdelpsi), exact incl. dv=0

        float sal   = rb - __ldg(&lengths[morig]);
        float sstar = S0 + mv * DTH + (mv * ndv) / (2.0f * sqrtf(AMAX * BB));
        float q  = mv / V0;
        float q2 = q * q;
        float afree = AMAX * (1.0f - q2 * q2);

        bool stop = (stopm >> lane) & 1u;
        float action;
        if (stop) {
            action = afree - AMAX;              // ratio = 1
        } else if (isinf(sal) || isnan(sal)) {
            action = afree;
        } else {
            float r = sstar / sal;
            action = afree - AMAX * r * r;
        }
        out[bat * NV + morig] = action;
    }
}

extern "C" void kernel_launch(void* const* d_in, const int* in_sizes, int n_in,
                              void* d_out, int out_size)
{
    const float* state   = (const float*)d_in[0];
    const float* lengths = (const float*)d_in[1];
    const float* v0      = (const float*)d_in[2];
    const float* s0      = (const float*)d_in[3];
    const float* dth     = (const float*)d_in[4];
    const float* amax    = (const float*)d_in[5];
    const float* b       = (const float*)d_in[6];
    float* out = (float*)d_out;

    prep_kernel<<<NB, 512>>>(state);
    dim3 grid(NV / (EPW * WPB), NB);
    rulepolicy_kernel<<<grid, BTHREADS>>>(lengths, v0, s0, dth, amax, b, out);
}

// round 14
// speedup vs baseline: 1.1801x; 1.1801x over previous
#include <cuda_runtime.h>
#include <math.h>

#define NV 1024
#define NB 16
#define GRID_DIM 16                 // 16x16 cells of 25m over [0,400)
#define NCELL (GRID_DIM * GRID_DIM)
#define EPW 4                       // egos per warp (consecutive in sorted order)
#define WPB 8                       // warps per block
#define BTHREADS (WPB * 32)         // 256

// Cell-sorted per-batch data
__device__ float4 g_sxycs[NB * NV];       // {x, y, cos, sin}
__device__ float  g_sv[NB * NV];          // v
__device__ int    g_sorig[NB * NV];       // sorted pos -> original index
__device__ int    g_cstart[NB * (NCELL + 1)];

// One block per batch: sincos + counting-sort into the 16x16 grid.
__global__ __launch_bounds__(512) void prep_kernel(const float* __restrict__ state)
{
    __shared__ int counts[NCELL];
    __shared__ int scan[NCELL];
    __shared__ int offs[NCELL];

    const int bat = blockIdx.x;
    const int t = threadIdx.x;
    const int base = bat * NV;
    const float* st = state + (size_t)bat * NV * 5;

    if (t < NCELL) counts[t] = 0;
    __syncthreads();

    float x[2], y[2], v[2], c[2], s[2];
    int cl[2];
    #pragma unroll
    for (int q = 0; q < 2; q++) {
        int i = t + q * 512;
        const float* p = st + i * 5;
        x[q] = p[0]; y[q] = p[1]; v[q] = p[2];
        float psi = p[3];
        sincosf(psi, &s[q], &c[q]);
        int cx = max(0, min(GRID_DIM - 1, (int)(x[q] * 0.04f)));
        int cy = max(0, min(GRID_DIM - 1, (int)(y[q] * 0.04f)));
        cl[q] = cy * GRID_DIM + cx;
        atomicAdd(&counts[cl[q]], 1);
    }
    __syncthreads();

    if (t < NCELL) scan[t] = counts[t];
    __syncthreads();
    for (int d = 1; d < NCELL; d <<= 1) {
        int val = 0;
        if (t < NCELL && t >= d) val = scan[t - d];
        __syncthreads();
        if (t < NCELL) scan[t] += val;
        __syncthreads();
    }
    if (t < NCELL) {
        int e = scan[t] - counts[t];               // exclusive
        offs[t] = e;
        g_cstart[bat * (NCELL + 1) + t] = e;
    }
    if (t == 0) g_cstart[bat * (NCELL + 1) + NCELL] = NV;
    __syncthreads();

    #pragma unroll
    for (int q = 0; q < 2; q++) {
        int i = t + q * 512;
        int p = atomicAdd(&offs[cl[q]], 1);
        g_sxycs[base + p] = make_float4(x[q], y[q], c[q], s[q]);
        g_sv[base + p] = v[q];
        g_sorig[base + p] = i;
    }
}

// One warp per 4 consecutive SORTED egos. Each lane loads one candidate and
// evaluates it against all 4 egos in registers. Outside an ego's 5x5 cell
// neighborhood dr>=50 so nd >= 50*cos20 = 46.98: best < 46.9 certifies the
// neighborhood result. Uncertified egos share ONE combined full-scan pass.
__global__ __launch_bounds__(BTHREADS)
void rulepolicy_kernel(const float* __restrict__ lengths,
                       const float* __restrict__ v0p,
                       const float* __restrict__ s0p,
                       const float* __restrict__ dthp,
                       const float* __restrict__ amaxp,
                       const float* __restrict__ bp,
                       float* __restrict__ out)
{
    const int lane = threadIdx.x & 31;
    const int wid = threadIdx.x >> 5;
    const int bat = blockIdx.y;
    const int base = bat * NV;
    const int eg0 = (blockIdx.x * WPB + wid) * EPW;   // first sorted ego pos

    const float C20SQ = 0.8830222215594891f;   // cos^2(20deg)
    const float C45   = 0.7071067811865476f;   // cos(45deg)
    const float INF   = __int_as_float(0x7f800000);
    const float TERM  = 46.9f;                 // < 50*cos20 = 46.984

    const int* cs = g_cstart + bat * (NCELL + 1);
    const float4* sd = g_sxycs + base;
    const float*  sv = g_sv + base;

    // Replicate the 4 egos into registers on every lane; lane e keeps ego e's
    // scalars for the epilogue.
    float ex[EPW], ey[EPW], ec[EPW], es[EPW], ev[EPW];
    float mc = 0, ms = 0, mv = 0;
    int   morig = 0;
    int cxmin = GRID_DIM - 1, cxmax = 0, cymin = GRID_DIM - 1, cymax = 0;
    #pragma unroll
    for (int e = 0; e < EPW; e++) {
        float4 a = __ldg(&sd[eg0 + e]);
        float  v = __ldg(&sv[eg0 + e]);
        ex[e] = a.x; ey[e] = a.y; ec[e] = a.z; es[e] = a.w; ev[e] = v;
        if (lane == e) {
            mc = a.z; ms = a.w; mv = v;
            morig = __ldg(&g_sorig[base + eg0 + e]);
        }
        int cx = max(0, min(GRID_DIM - 1, (int)(a.x * 0.04f)));
        int cy = max(0, min(GRID_DIM - 1, (int)(a.y * 0.04f)));
        cxmin = min(cxmin, cx); cxmax = max(cxmax, cx);
        cymin = min(cymin, cy); cymax = max(cymax, cy);
    }

    float best[EPW];
    int   bidx[EPW];
    unsigned stopm = 0;
    #pragma unroll
    for (int e = 0; e < EPW; e++) { best[e] = INF; bidx[e] = 0; }

    // ── Union-neighborhood scan: leader + stop fused, 4 egos per candidate ──
    {
        int x0 = max(cxmin - 2, 0), x1 = min(cxmax + 2, GRID_DIM - 1);
        int y0 = max(cymin - 2, 0), y1 = min(cymax + 2, GRID_DIM - 1);
        for (int ry = y0; ry <= y1; ry++) {
            int beg = __ldg(&cs[ry * GRID_DIM + x0]);
            int end = __ldg(&cs[ry * GRID_DIM + x1 + 1]);
            for (int i = beg + lane; i < end; i += 32) {
                float4 a = __ldg(&sd[i]);
                float vi = __ldg(&sv[i]);
                #pragma unroll
                for (int e = 0; e < EPW; e++) {
                    float dx = a.x - ex[e], dy = a.y - ey[e];
                    float r2 = fmaf(dx, dx, dy * dy);
                    float nd = fmaf(dx, ec[e], dy * es[e]);   // dr*cos(delpsi)
                    float n2 = nd * nd;
                    float m  = fminf(nd, fmaf(-C20SQ, r2, n2));
                    float vv = (m > 0.0f) ? nd : INF;
                    bool  c  = vv < best[e];
                    best[e] = c ? vv : best[e];
                    bidx[e] = c ? i : bidx[e];
                    float cpd = fmaf(a.z, ec[e], a.w * es[e]); // cos(psi_i-psi_j)
                    bool sc = (r2 < 400.0f) & (nd > 0.0f) & (n2 > 0.25f * r2)
                              & (cpd < C45) & (vi > ev[e]);
                    stopm |= sc ? (1u << e) : 0u;
                }
            }
        }
    }

    // ── Reductions via REDUX (min float-bits, then min index among ties) ──
    stopm = __reduce_or_sync(0xFFFFFFFFu, stopm);

    float rb = 0.0f;  // lane e holds ego e's reduced best
    int   ri = 0;
    #pragma unroll
    for (int e = 0; e < EPW; e++) {
        unsigned vb = __float_as_uint(best[e]);       // >=0 or INF: order-preserving
        unsigned mn = __reduce_min_sync(0xFFFFFFFFu, vb);
        unsigned cand = (vb == mn) ? (unsigned)bidx[e] : 0xFFFFFFFFu;
        unsigned mi = __reduce_min_sync(0xFFFFFFFFu, cand);
        if (lane == e) { rb = __uint_as_float(mn); ri = (int)mi; }
    }

    // ── Combined fallback: ONE full pass for all uncertified egos ──
    unsigned need = __ballot_sync(0xFFFFFFFFu, (lane < EPW) && (rb >= TERM));
    if (need) {
        float fb[EPW];
        int   fi[EPW];
        #pragma unroll
        for (int e = 0; e < EPW; e++) { fb[e] = INF; fi[e] = 0; }
        for (int i = lane; i < NV; i += 32) {
            float4 a = __ldg(&sd[i]);
            #pragma unroll
            for (int e = 0; e < EPW; e++) {
                if (need & (1u << e)) {
                    float dx = a.x - ex[e], dy = a.y - ey[e];
                    float r2 = fmaf(dx, dx, dy * dy);
                    float nd = fmaf(dx, ec[e], dy * es[e]);
                    float m  = fminf(nd, fmaf(-C20SQ, r2, nd * nd));
                    float vv = (m > 0.0f) ? nd : INF;
                    bool  c  = vv < fb[e];
                    fb[e] = c ? vv : fb[e];
                    fi[e] = c ? i : fi[e];
                }
            }
        }
        #pragma unroll
        for (int e = 0; e < EPW; e++) {
            if (need & (1u << e)) {
                unsigned vb = __float_as_uint(fb[e]);
                unsigned mn = __reduce_min_sync(0xFFFFFFFFu, vb);
                unsigned cand = (vb == mn) ? (unsigned)fi[e] : 0xFFFFFFFFu;
                unsigned mi = __reduce_min_sync(0xFFFFFFFFu, cand);
                if (lane == e) { rb = __uint_as_float(mn); ri = (int)mi; }
            }
        }
    }

    // ── Epilogue: lane e finishes ego e ──
    if (lane < EPW) {
        const float V0 = __ldg(&v0p[0]), S0 = __ldg(&s0p[0]), DTH = __ldg(&dthp[0]);
        const float AMAX = __ldg(&amaxp[0]), BB = __ldg(&bp[0]);

        float4 ld = __ldg(&sd[ri]);             // leader {x, y, cos, sin}
        float  vl = __ldg(&sv[ri]);
        float dvx = vl * ld.z - mv * mc;
        float dvy = vl * ld.w - mv * ms;
        float ndv = fmaf(dvx, mc, dvy * ms);    // dv*cos(vdelpsi), exact incl. dv=0

        float sal   = rb - __ldg(&lengths[morig]);
        float sstar = S0 + mv * DTH + (mv * ndv) / (2.0f * sqrtf(AMAX * BB));
        float q  = mv / V0;
        float q2 = q * q;
        float afree = AMAX * (1.0f - q2 * q2);

        bool stop = (stopm >> lane) & 1u;
        float action;
        if (stop) {
            action = afree - AMAX;              // ratio = 1
        } else if (isinf(sal) || isnan(sal)) {
            action = afree;
        } else {
            float r = sstar / sal;
            action = afree - AMAX * r * r;
        }
        out[bat * NV + morig] = action;
    }
}

extern "C" void kernel_launch(void* const* d_in, const int* in_sizes, int n_in,
                              void* d_out, int out_size)
{
    const float* state   = (const float*)d_in[0];
    const float* lengths = (const float*)d_in[1];
    const float* v0      = (const float*)d_in[2];
    const float* s0      = (const float*)d_in[3];
    const float* dth     = (const float*)d_in[4];
    const float* amax    = (const float*)d_in[5];
    const float* b       = (const float*)d_in[6];
    float* out = (float*)d_out;

    prep_kernel<<<NB, 512>>>(state);
    dim3 grid(NV / (EPW * WPB), NB);
    rulepolicy_kernel<<<grid, BTHREADS>>>(lengths, v0, s0, dth, amax, b, out);
}

// round 15
// speedup vs baseline: 1.2980x; 1.0998x over previous
#include <cuda_runtime.h>
#include <math.h>

#define NV 1024
#define NB 16
#define GRID_DIM 16                 // 16x16 cells of 25m over [0,400)
#define NCELL 256
#define CPB 8                       // cells per block
#define NBLK (NCELL / CPB)          // 32 blocks per batch
#define THREADS 256

__global__ __launch_bounds__(THREADS)
void rulepolicy_fused(const float* __restrict__ state,
                      const float* __restrict__ lengths,
                      const float* __restrict__ v0p,
                      const float* __restrict__ s0p,
                      const float* __restrict__ dthp,
                      const float* __restrict__ amaxp,
                      const float* __restrict__ bp,
                      float* __restrict__ out)
{
    __shared__ int counts[NCELL];
    __shared__ int scanbuf[NCELL];
    __shared__ int offs[NCELL];
    __shared__ int cstart[NCELL + 1];
    __shared__ float4 sd[NV];        // sorted {x, y, cos, sin}  (16 KB)
    __shared__ float  svv[NV];       // sorted v                  (4 KB)
    __shared__ int    sorig[NV];     // sorted -> original index  (4 KB)

    const int bat = blockIdx.y;
    const int kb  = blockIdx.x;      // owns cells [kb*CPB, kb*CPB+CPB)
    const int t = threadIdx.x;
    const float* st = state + (size_t)bat * NV * 5;

    // ── Redundant per-block prep: sincos + counting-sort of this batch ──
    counts[t] = 0;
    __syncthreads();

    float x[4], y[4], v[4], cc[4], ssn[4];
    int cl[4];
    #pragma unroll
    for (int q = 0; q < 4; q++) {
        int i = t + q * THREADS;
        const float* p = st + i * 5;
        x[q] = p[0]; y[q] = p[1]; v[q] = p[2];
        float psi = p[3];
        sincosf(psi, &ssn[q], &cc[q]);
        int cx = max(0, min(GRID_DIM - 1, (int)(x[q] * 0.04f)));
        int cy = max(0, min(GRID_DIM - 1, (int)(y[q] * 0.04f)));
        cl[q] = cy * GRID_DIM + cx;
        atomicAdd(&counts[cl[q]], 1);
    }
    __syncthreads();

    scanbuf[t] = counts[t];
    __syncthreads();
    #pragma unroll
    for (int d = 1; d < NCELL; d <<= 1) {
        int vv = (t >= d) ? scanbuf[t - d] : 0;
        __syncthreads();
        scanbuf[t] += vv;
        __syncthreads();
    }
    offs[t] = scanbuf[t] - counts[t];      // exclusive
    cstart[t + 1] = scanbuf[t];
    if (t == 0) cstart[0] = 0;
    __syncthreads();

    #pragma unroll
    for (int q = 0; q < 4; q++) {
        int i = t + q * THREADS;
        int pos = atomicAdd(&offs[cl[q]], 1);
        sd[pos] = make_float4(x[q], y[q], cc[q], ssn[q]);
        svv[pos] = v[q];
        sorig[pos] = i;
    }
    __syncthreads();

    // ── Ego processing: warps round-robin over this block's sorted range ──
    const float C20SQ = 0.8830222215594891f;   // cos^2(20deg)
    const float C45   = 0.7071067811865476f;   // cos(45deg)
    const float INF   = __int_as_float(0x7f800000);
    const float TERM  = 46.9f;                 // < 50*cos20 = 46.984

    const float V0 = __ldg(&v0p[0]), S0 = __ldg(&s0p[0]), DTH = __ldg(&dthp[0]);
    const float AMAX = __ldg(&amaxp[0]), BB = __ldg(&bp[0]);
    const float DEN = 2.0f * sqrtf(AMAX * BB);

    const int lane = t & 31;
    const int w = t >> 5;
    const int c0 = cstart[kb * CPB];
    const int c1 = cstart[kb * CPB + CPB];

    for (int p = c0 + w; p < c1; p += THREADS / 32) {
        float4 eg = sd[p];                      // broadcast LDS
        float vj = svv[p];
        float xj = eg.x, yj = eg.y, cj = eg.z, sj = eg.w;
        int cx = max(0, min(GRID_DIM - 1, (int)(xj * 0.04f)));
        int cy = max(0, min(GRID_DIM - 1, (int)(yj * 0.04f)));
        int X0 = max(cx - 2, 0), X1 = min(cx + 2, GRID_DIM - 1);
        int Y0 = max(cy - 2, 0), Y1 = min(cy + 2, GRID_DIM - 1);

        float best = INF;
        int   bidx = 0;
        int   stopi = 0;

        for (int ry = Y0; ry <= Y1; ry++) {
            int beg = cstart[ry * GRID_DIM + X0];
            int end = cstart[ry * GRID_DIM + X1 + 1];
            for (int i = beg + lane; i < end; i += 32) {
                float4 a = sd[i];
                float vi = svv[i];
                float dx = a.x - xj, dy = a.y - yj;
                float r2 = fmaf(dx, dx, dy * dy);
                float nd = fmaf(dx, cj, dy * sj);      // dr*cos(delpsi)
                float n2 = nd * nd;
                float m  = fminf(nd, fmaf(-C20SQ, r2, n2));
                float e  = (m > 0.0f) ? nd : INF;
                bool  c  = e < best;
                best = c ? e : best;  bidx = c ? i : bidx;
                float cpd = fmaf(a.z, cj, a.w * sj);   // cos(psi_i-psi_j)
                // dr<20 & |delpsi|<60 (nd>0 & n2>r2/4) & |dpsi|>45 & v_i>v_j
                stopi |= (int)((r2 < 400.0f) & (nd > 0.0f) & (n2 > 0.25f * r2)
                               & (cpd < C45) & (vi > vj));
            }
        }

        // Warp reductions (REDUX): OR for stop; min float-bits then min index.
        stopi = (int)__reduce_or_sync(0xFFFFFFFFu, (unsigned)stopi);
        unsigned vb = __float_as_uint(best);           // >=0 or INF: order-preserving
        unsigned mn = __reduce_min_sync(0xFFFFFFFFu, vb);
        unsigned cd = (vb == mn) ? (unsigned)bidx : 0xFFFFFFFFu;
        unsigned mi = __reduce_min_sync(0xFFFFFFFFu, cd);
        best = __uint_as_float(mn);
        bidx = (int)mi;

        // Rare fallback: outside the 5x5, dr>50 so nd>46.98 — only needed if
        // the neighborhood couldn't certify (best >= TERM). Lean smem scan.
        if (best >= TERM) {
            float fb = best; int fi = bidx;
            for (int i = lane; i < NV; i += 32) {
                float4 a = sd[i];
                float dx = a.x - xj, dy = a.y - yj;
                float r2 = fmaf(dx, dx, dy * dy);
                float nd = fmaf(dx, cj, dy * sj);
                float m  = fminf(nd, fmaf(-C20SQ, r2, nd * nd));
                float e  = (m > 0.0f) ? nd : INF;
                bool  c  = e < fb;
                fb = c ? e : fb;  fi = c ? i : fi;
            }
            unsigned vb2 = __float_as_uint(fb);
            unsigned mn2 = __reduce_min_sync(0xFFFFFFFFu, vb2);
            unsigned cd2 = (vb2 == mn2) ? (unsigned)fi : 0xFFFFFFFFu;
            unsigned mi2 = __reduce_min_sync(0xFFFFFFFFu, cd2);
            best = __uint_as_float(mn2);
            bidx = (int)mi2;
        }

        if (lane == 0) {
            float4 ld = sd[bidx];                   // leader {x,y,cos,sin}
            float  vl = svv[bidx];
            float dvx = vl * ld.z - vj * cj;
            float dvy = vl * ld.w - vj * sj;
            float ndv = fmaf(dvx, cj, dvy * sj);    // dv*cos(vdelpsi)

            int orig = sorig[p];
            float sal   = best - __ldg(&lengths[orig]);
            float sstar = S0 + vj * DTH + (vj * ndv) / DEN;
            float q  = vj / V0;
            float q2 = q * q;
            float afree = AMAX * (1.0f - q2 * q2);

            float action;
            if (stopi) {
                action = afree - AMAX;              // ratio = 1
            } else if (isinf(sal) || isnan(sal)) {
                action = afree;
            } else {
                float r = sstar / sal;
                action = afree - AMAX * r * r;
            }
            out[bat * NV + orig] = action;
        }
    }
}

extern "C" void kernel_launch(void* const* d_in, const int* in_sizes, int n_in,
                              void* d_out, int out_size)
{
    const float* state   = (const float*)d_in[0];
    const float* lengths = (const float*)d_in[1];
    const float* v0      = (const float*)d_in[2];
    const float* s0      = (const float*)d_in[3];
    const float* dth     = (const float*)d_in[4];
    const float* amax    = (const float*)d_in[5];
    const float* b       = (const float*)d_in[6];
    float* out = (float*)d_out;

    dim3 grid(NBLK, NB);
    rulepolicy_fused<<<grid, THREADS>>>(state, lengths, v0, s0, dth, amax, b, out);
}